// round 11
// baseline (speedup 1.0000x reference)
#include <cuda_runtime.h>
#include <cuda_fp16.h>
#include <math.h>
#include <cstdint>

#define B 64
#define S 4096
#define E 512
#define D 512
#define H 512
#define NEGV (-1.0e9f)

// ---------------------------------------------------------------------------
// Scratch (no cudaMalloc allowed)
// ---------------------------------------------------------------------------
__device__ float g_decoded[B * H];            // 128 KB
__device__ float g_attn_part[B * 32 * E];     // 4 MB
// W_enc^T split hi/lo fp16, packed in m16n8k16 B-fragment order (as R7)
__device__ uint4 g_WBh[32 * 64 * 32];         // 1 MB
// enc pre-split fp16 planes, row-major [B*S][E]
__device__ __half g_Ah[(long)B * S * E];      // 256 MB
__device__ __half g_Al[(long)B * S * E];      // 256 MB

// ---------------------------------------------------------------------------
// helpers
// ---------------------------------------------------------------------------
__device__ __forceinline__ uint32_t smem_u32(const void* p) {
    uint32_t a;
    asm("{ .reg .u64 t; cvta.to.shared.u64 t, %1; cvt.u32.u64 %0, t; }"
        : "=r"(a) : "l"(p));
    return a;
}
__device__ __forceinline__ float tanh_fast(float x) {
    float e;
    asm("ex2.approx.f32 %0, %1;" : "=f"(e) : "f"(x * 2.8853900817779268f));
    float r;
    asm("rcp.approx.f32 %0, %1;" : "=f"(r) : "f"(e + 1.0f));
    return fmaf(-2.0f, r, 1.0f);
}
__device__ __forceinline__ void split_h2(float x, float y,
                                         uint32_t& hi, uint32_t& lo) {
    half2 h2 = __floats2half2_rn(x, y);
    float2 hf = __half22float2(h2);
    half2 l2 = __floats2half2_rn(x - hf.x, y - hf.y);
    hi = *(uint32_t*)&h2;
    lo = *(uint32_t*)&l2;
}
#define MMA_F16(d, a, b0, b1) \
    asm volatile( \
        "mma.sync.aligned.m16n8k16.row.col.f32.f16.f16.f32 " \
        "{%0,%1,%2,%3}, {%4,%5,%6,%7}, {%8,%9}, {%0,%1,%2,%3};" \
        : "+f"((d)[0]), "+f"((d)[1]), "+f"((d)[2]), "+f"((d)[3]) \
        : "r"((a)[0]), "r"((a)[1]), "r"((a)[2]), "r"((a)[3]), \
          "r"(b0), "r"(b1))

#define LDSM_X4(r, addr) \
    asm volatile("ldmatrix.sync.aligned.m8n8.x4.shared.b16 {%0,%1,%2,%3}, [%4];" \
                 : "=r"((r)[0]), "=r"((r)[1]), "=r"((r)[2]), "=r"((r)[3]) \
                 : "r"(addr))

#define CP_ASYNC16(dst, src) \
    asm volatile("cp.async.cg.shared.global [%0], [%1], 16;" \
                 :: "r"(dst), "l"(src) : "memory")
#define CP_COMMIT()  asm volatile("cp.async.commit_group;" ::: "memory")
#define CP_WAIT(n)   asm volatile("cp.async.wait_group %0;" :: "n"(n) : "memory")

// ---------------------------------------------------------------------------
// Kernel 0a: W_enc [E,H] -> g_WBh (transposed, fp16 hi/lo, fragment order)
// ---------------------------------------------------------------------------
__global__ void wsplit_kernel(const float* __restrict__ W_enc) {
    int idx = blockIdx.x * 256 + threadIdx.x;   // 65536 total
    int lane = idx & 31;
    int n8   = (idx >> 5) & 63;
    int k16  = idx >> 11;
    int k0 = k16 * 16 + (lane & 3) * 2;
    int n  = n8 * 8 + (lane >> 2);
    float v0 = W_enc[(k0    ) * H + n];
    float v1 = W_enc[(k0 + 1) * H + n];
    float v2 = W_enc[(k0 + 8) * H + n];
    float v3 = W_enc[(k0 + 9) * H + n];
    uint4 o;
    split_h2(v0, v1, o.x, o.z);
    split_h2(v2, v3, o.y, o.w);
    g_WBh[idx] = o;
}

// ---------------------------------------------------------------------------
// Kernel 0b: enc -> fp16 hi/lo planes (coalesced, 8 floats per thread)
// ---------------------------------------------------------------------------
__global__ void asplit_kernel(const float* __restrict__ enc) {
    long i8 = ((long)blockIdx.x * 256 + threadIdx.x) * 8;
    float4 v0 = *(const float4*)(enc + i8);
    float4 v1 = *(const float4*)(enc + i8 + 4);
    uint4 hi, lo;
    split_h2(v0.x, v0.y, hi.x, lo.x);
    split_h2(v0.z, v0.w, hi.y, lo.y);
    split_h2(v1.x, v1.y, hi.z, lo.z);
    split_h2(v1.z, v1.w, hi.w, lo.w);
    *(uint4*)(g_Ah + i8) = hi;
    *(uint4*)(g_Al + i8) = lo;
}

// ---------------------------------------------------------------------------
// Kernel 1: decoded[b,h] = dec[b,:] @ W_dec[:,h]
// ---------------------------------------------------------------------------
__global__ void decode_kernel(const float* __restrict__ dec,
                              const float* __restrict__ W_dec) {
    int b = blockIdx.x;
    int t = threadIdx.x;
    __shared__ float ds[D];
    ds[t] = dec[b * D + t];
    __syncthreads();
    float sum = 0.f;
#pragma unroll 8
    for (int d = 0; d < D; d++) sum += ds[d] * W_dec[d * H + t];
    g_decoded[b * H + t] = sum;
}

// ---------------------------------------------------------------------------
// Kernel 2: logits via mma.sync fp16x3, pre-split A planes + ldmatrix
// grid = B*(S/128) = 2048 blocks, 256 threads (8 warps: 4 m-warps x 2 n-warps)
// A smem: [128 rows][40 halves] per plane (80B row stride, LDSM conflict-free)
// ---------------------------------------------------------------------------
#define AROW 40   // halves per smem row (32 data + 8 pad)

__global__ void __launch_bounds__(256, 2)
logits_mma_kernel(const float* __restrict__ W_out,
                  float* __restrict__ logits) {
    __shared__ float s_dec[H];
    __shared__ float s_wout[H];
    __shared__ float s_part[256];
    __shared__ __align__(128) __half sAh[2][128 * AROW];   // 2 x 10KB
    __shared__ __align__(128) __half sAl[2][128 * AROW];   // 2 x 10KB

    int tid = threadIdx.x;
    int lane = tid & 31;
    int wid = tid >> 5;
    int mw = wid & 3;     // 0..3  -> rows mw*32..
    int nw = wid >> 2;    // 0..1  -> n8 offset nw*8 within the 128-col chunk

    int b  = blockIdx.x >> 5;
    int st = blockIdx.x & 31;
    long rowbase = (long)b * S + (long)st * 128;

    for (int i = tid; i < H; i += 256) {
        s_dec[i]  = g_decoded[b * H + i];
        s_wout[i] = W_out[i];
    }

    const uint4* gB = g_WBh;
    float rowsum[4] = {0.f, 0.f, 0.f, 0.f};

    // ldmatrix per-lane byte offset within a plane buffer:
    // row = mw*32 + (lane&15) (+ mi*16), chunk c = (lane>>4) (+ kk*2)
    uint32_t laneoff = (uint32_t)((mw * 32 + (lane & 15)) * AROW +
                                  (lane >> 4) * 8) * 2;
    uint32_t ah0 = smem_u32(&sAh[0][0]), ah1 = smem_u32(&sAh[1][0]);
    uint32_t al0 = smem_u32(&sAl[0][0]), al1 = smem_u32(&sAl[1][0]);

    // staging: 2 chunks per plane per thread per kc (4 cp.async total)
    auto stageA = [&](int kc, int buf) {
#pragma unroll
        for (int it = 0; it < 2; it++) {
            int f = tid + it * 256;          // 0..511
            int row = f >> 2, c = f & 3;
            const __half* srcH = g_Ah + (rowbase + row) * E + kc * 32 + c * 8;
            const __half* srcL = g_Al + (rowbase + row) * E + kc * 32 + c * 8;
            uint32_t d1 = smem_u32(&sAh[buf][row * AROW + c * 8]);
            uint32_t d2 = smem_u32(&sAl[buf][row * AROW + c * 8]);
            CP_ASYNC16(d1, srcH);
            CP_ASYNC16(d2, srcL);
        }
        CP_COMMIT();
    };

    for (int nc = 0; nc < 4; nc++) {
        float acc[2][8][4];
#pragma unroll
        for (int mi = 0; mi < 2; mi++)
#pragma unroll
            for (int j = 0; j < 8; j++)
#pragma unroll
                for (int r = 0; r < 4; r++) acc[mi][j][r] = 0.f;

        int n8base = nc * 16 + nw * 8;

        stageA(0, 0);

        for (int kc = 0; kc < 16; kc++) {
            if (kc < 15) { stageA(kc + 1, (kc + 1) & 1); CP_WAIT(1); }
            else         { CP_WAIT(0); }
            __syncthreads();
            uint32_t aBaseH = ((kc & 1) ? ah1 : ah0) + laneoff;
            uint32_t aBaseL = ((kc & 1) ? al1 : al0) + laneoff;

#pragma unroll
            for (int kk = 0; kk < 2; kk++) {
                int k16 = kc * 2 + kk;
                // B fragments for this k16 (8-wide MLP, same as R7)
                uint4 bc[8];
#pragma unroll
                for (int j = 0; j < 8; j++)
                    bc[j] = gB[(k16 * 64 + n8base + j) * 32 + lane];

                // A fragments via ldmatrix (both mi tiles up front, R7 order)
                uint32_t aH[2][4], aL[2][4];
#pragma unroll
                for (int mi = 0; mi < 2; mi++) {
                    uint32_t off = (uint32_t)(mi * 16 * AROW * 2 + kk * 32);
                    LDSM_X4(aH[mi], aBaseH + off);
                    LDSM_X4(aL[mi], aBaseL + off);
                }

                // hi*hi
#pragma unroll
                for (int mi = 0; mi < 2; mi++)
#pragma unroll
                    for (int j = 0; j < 8; j++)
                        MMA_F16(acc[mi][j], aH[mi], bc[j].x, bc[j].y);
                // lo*hi
#pragma unroll
                for (int mi = 0; mi < 2; mi++)
#pragma unroll
                    for (int j = 0; j < 8; j++)
                        MMA_F16(acc[mi][j], aL[mi], bc[j].x, bc[j].y);
                // hi*lo
#pragma unroll
                for (int mi = 0; mi < 2; mi++)
#pragma unroll
                    for (int j = 0; j < 8; j++)
                        MMA_F16(acc[mi][j], aH[mi], bc[j].z, bc[j].w);
            }
            __syncthreads();
        }

        // epilogue for this N-chunk: tanh(acc + dec) * wout -> rowsum
#pragma unroll
        for (int mi = 0; mi < 2; mi++)
#pragma unroll
            for (int j = 0; j < 8; j++)
#pragma unroll
                for (int r = 0; r < 4; r++) {
                    int col = nc * 128 + nw * 64 + j * 8 + (lane & 3) * 2 + (r & 1);
                    float x = acc[mi][j][r] + s_dec[col];
                    rowsum[mi * 2 + (r >> 1)] += tanh_fast(x) * s_wout[col];
                }
    }

    // reduce rowsum: over lane&3 (shfl), then over nw (smem)
#pragma unroll
    for (int i = 0; i < 4; i++) {
        float v = rowsum[i];
        v += __shfl_xor_sync(0xffffffffu, v, 1);
        v += __shfl_xor_sync(0xffffffffu, v, 2);
        rowsum[i] = v;
    }
    if ((lane & 3) == 0) {
#pragma unroll
        for (int i = 0; i < 4; i++) {
            int row = mw * 32 + (i >> 1) * 16 + (lane >> 2) + (i & 1) * 8;
            s_part[nw * 128 + row] = rowsum[i];
        }
    }
    __syncthreads();
    if (tid < 128)
        logits[rowbase + tid] = s_part[tid] + s_part[128 + tid];
}

// ---------------------------------------------------------------------------
// Kernel 3: masked softmax over S, in place
// ---------------------------------------------------------------------------
__global__ void softmax_kernel(const int* __restrict__ mask,
                               float* __restrict__ probs) {
    int b = blockIdx.x;
    int t = threadIdx.x;
    __shared__ float red[32];
    float l[4];
#pragma unroll
    for (int i = 0; i < 4; i++) {
        int s = t + i * 1024;
        float v = probs[(long)b * S + s];
        l[i] = (mask[(long)b * S + s] == 0) ? NEGV : v;
    }
    float m = fmaxf(fmaxf(l[0], l[1]), fmaxf(l[2], l[3]));
#pragma unroll
    for (int off = 16; off > 0; off >>= 1)
        m = fmaxf(m, __shfl_xor_sync(0xffffffffu, m, off));
    if ((t & 31) == 0) red[t >> 5] = m;
    __syncthreads();
    if (t < 32) {
        float v = red[t];
#pragma unroll
        for (int off = 16; off > 0; off >>= 1)
            v = fmaxf(v, __shfl_xor_sync(0xffffffffu, v, off));
        red[t] = v;
    }
    __syncthreads();
    m = red[0];
    __syncthreads();
    float e[4];
    float sum = 0.f;
#pragma unroll
    for (int i = 0; i < 4; i++) { e[i] = expf(l[i] - m); sum += e[i]; }
#pragma unroll
    for (int off = 16; off > 0; off >>= 1)
        sum += __shfl_xor_sync(0xffffffffu, sum, off);
    if ((t & 31) == 0) red[t >> 5] = sum;
    __syncthreads();
    if (t < 32) {
        float v = red[t];
#pragma unroll
        for (int off = 16; off > 0; off >>= 1)
            v += __shfl_xor_sync(0xffffffffu, v, off);
        red[t] = v;
    }
    __syncthreads();
    float inv = 1.f / red[0];
#pragma unroll
    for (int i = 0; i < 4; i++)
        probs[(long)b * S + t + i * 1024] = e[i] * inv;
}

// ---------------------------------------------------------------------------
// Kernel 4: partial attn over 128-row s-chunks, float4 per thread
// ---------------------------------------------------------------------------
__global__ void attn_part_kernel(const float* __restrict__ enc,
                                 const float* __restrict__ probs) {
    int sc = blockIdx.x & 31;
    int b  = blockIdx.x >> 5;
    int t  = threadIdx.x;   // 0..127
    __shared__ float p_s[128];
    p_s[t] = probs[(long)b * S + sc * 128 + t];
    __syncthreads();
    const float4* encp = (const float4*)(enc + ((long)b * S + (long)sc * 128) * E) + t;
    float4 acc = make_float4(0.f, 0.f, 0.f, 0.f);
#pragma unroll 8
    for (int s = 0; s < 128; s++) {
        float4 v = encp[(long)s * (E / 4)];
        float p = p_s[s];
        acc.x += p * v.x; acc.y += p * v.y;
        acc.z += p * v.z; acc.w += p * v.w;
    }
    ((float4*)g_attn_part)[((long)b * 32 + sc) * (E / 4) + t] = acc;
}

// ---------------------------------------------------------------------------
// Kernel 5: fixed-order reduction -> attn (float4)
// ---------------------------------------------------------------------------
__global__ void attn_reduce_kernel(float* __restrict__ attn) {
    int b = blockIdx.x;
    int t = threadIdx.x;   // 0..127
    float4 s = make_float4(0.f, 0.f, 0.f, 0.f);
#pragma unroll
    for (int c = 0; c < 32; c++) {
        float4 v = ((const float4*)g_attn_part)[((long)b * 32 + c) * (E / 4) + t];
        s.x += v.x; s.y += v.y; s.z += v.z; s.w += v.w;
    }
    ((float4*)attn)[b * (E / 4) + t] = s;
}

// ---------------------------------------------------------------------------
extern "C" void kernel_launch(void* const* d_in, const int* in_sizes, int n_in,
                              void* d_out, int out_size) {
    const float* enc   = (const float*)d_in[0];
    const float* dec   = (const float*)d_in[1];
    const int*   mask  = (const int*)  d_in[2];
    const float* W_enc = (const float*)d_in[3];
    const float* W_dec = (const float*)d_in[4];
    const float* W_out = (const float*)d_in[5];

    float* attn  = (float*)d_out;       // [B,E]
    float* probs = attn + B * E;        // [B,S] (logits written in place)

    wsplit_kernel<<<256, 256>>>(W_enc);
    asplit_kernel<<<(int)(((long)B * S * E / 8) / 256), 256>>>(enc);
    decode_kernel<<<B, 512>>>(dec, W_dec);
    logits_mma_kernel<<<B * (S / 128), 256>>>(W_out, probs);
    softmax_kernel<<<B, 1024>>>(mask, probs);
    attn_part_kernel<<<B * 32, 128>>>(enc, probs);
    attn_reduce_kernel<<<B, 128>>>(attn);
}

// round 12
// speedup vs baseline: 1.3192x; 1.3192x over previous
#include <cuda_runtime.h>
#include <cuda_fp16.h>
#include <math.h>
#include <cstdint>

#define B 64
#define S 4096
#define E 512
#define D 512
#define H 512
#define NEGV (-1.0e9f)

// ---------------------------------------------------------------------------
// Scratch (no cudaMalloc allowed)
// ---------------------------------------------------------------------------
__device__ float g_decoded[B * H];            // 128 KB
__device__ float g_attn_part[B * 32 * E];     // 4 MB
// W_enc^T split hi/lo fp16, packed in m16n8k16 B-fragment order:
// uint4 { hi(k0,k0+1), hi(k0+8,k0+9), lo(k0,k0+1), lo(k0+8,k0+9) }
// at index (k16*64 + n8)*32 + lane
__device__ uint4 g_WBh[32 * 64 * 32];         // 1 MB

// ---------------------------------------------------------------------------
// helpers
// ---------------------------------------------------------------------------
__device__ __forceinline__ uint32_t smem_u32(const void* p) {
    uint32_t a;
    asm("{ .reg .u64 t; cvta.to.shared.u64 t, %1; cvt.u32.u64 %0, t; }"
        : "=r"(a) : "l"(p));
    return a;
}
__device__ __forceinline__ float tanh_fast(float x) {
    float e;
    asm("ex2.approx.f32 %0, %1;" : "=f"(e) : "f"(x * 2.8853900817779268f));
    float r;
    asm("rcp.approx.f32 %0, %1;" : "=f"(r) : "f"(e + 1.0f));
    return fmaf(-2.0f, r, 1.0f);
}
// split float2 -> fp16 hi pair + fp16 lo pair (packed half2 as u32)
__device__ __forceinline__ void split_h2(float x, float y,
                                         uint32_t& hi, uint32_t& lo) {
    half2 h2 = __floats2half2_rn(x, y);
    float2 hf = __half22float2(h2);
    half2 l2 = __floats2half2_rn(x - hf.x, y - hf.y);
    hi = *(uint32_t*)&h2;
    lo = *(uint32_t*)&l2;
}
#define MMA_F16(d, a, b0, b1) \
    asm volatile( \
        "mma.sync.aligned.m16n8k16.row.col.f32.f16.f16.f32 " \
        "{%0,%1,%2,%3}, {%4,%5,%6,%7}, {%8,%9}, {%0,%1,%2,%3};" \
        : "+f"((d)[0]), "+f"((d)[1]), "+f"((d)[2]), "+f"((d)[3]) \
        : "r"((a)[0]), "r"((a)[1]), "r"((a)[2]), "r"((a)[3]), \
          "r"(b0), "r"(b1))

#define CP_ASYNC16(dst, src) \
    asm volatile("cp.async.cg.shared.global [%0], [%1], 16;" \
                 :: "r"(dst), "l"(src) : "memory")
#define CP_COMMIT()  asm volatile("cp.async.commit_group;" ::: "memory")
#define CP_WAIT(n)   asm volatile("cp.async.wait_group %0;" :: "n"(n) : "memory")

// A smem swizzle: float index for logical (row, col) in a 128x32 tile
__device__ __forceinline__ int a_idx(int r, int c) {
    return r * 32 + ((((c >> 2) ^ (r & 7)) << 2) | (c & 3));
}

// ---------------------------------------------------------------------------
// Kernel 0: W_enc [E,H] -> g_WBh (transposed, fp16 hi/lo, fragment order)
// ---------------------------------------------------------------------------
__global__ void wsplit_kernel(const float* __restrict__ W_enc) {
    int idx = blockIdx.x * 256 + threadIdx.x;   // 65536 total
    int lane = idx & 31;
    int n8   = (idx >> 5) & 63;
    int k16  = idx >> 11;
    int k0 = k16 * 16 + (lane & 3) * 2;
    int n  = n8 * 8 + (lane >> 2);
    float v0 = W_enc[(k0    ) * H + n];
    float v1 = W_enc[(k0 + 1) * H + n];
    float v2 = W_enc[(k0 + 8) * H + n];
    float v3 = W_enc[(k0 + 9) * H + n];
    uint4 o;
    split_h2(v0, v1, o.x, o.z);
    split_h2(v2, v3, o.y, o.w);
    g_WBh[idx] = o;
}

// ---------------------------------------------------------------------------
// Kernel 1: decoded[b,h] = dec[b,:] @ W_dec[:,h]
// ---------------------------------------------------------------------------
__global__ void decode_kernel(const float* __restrict__ dec,
                              const float* __restrict__ W_dec) {
    int b = blockIdx.x;
    int t = threadIdx.x;
    __shared__ float ds[D];
    ds[t] = dec[b * D + t];
    __syncthreads();
    float sum = 0.f;
#pragma unroll 8
    for (int d = 0; d < D; d++) sum += ds[d] * W_dec[d * H + t];
    g_decoded[b * H + t] = sum;
}

// ---------------------------------------------------------------------------
// Kernel 2: logits via mma.sync fp16x3, 2 CTAs/SM, A+B cp.async double-buffer
// grid = B*(S/128) = 2048 blocks, 256 threads (8 warps: 4 m-warps x 2 n-warps)
// dynamic smem (floats):
//   [0     ..  8192)  sA[2][128*32]   raw fp32, xor-swizzled
//   [8192  .. 16384)  sB[2][1024 uint4]  fp16 frag-order (16KB per buffer)
//   [16384 .. 16896)  s_dec
//   [16896 .. 17408)  s_wout
//   [17408 .. 17664)  s_part
// ---------------------------------------------------------------------------
#define SMF_TOTAL (17664 * 4)

__global__ void __launch_bounds__(256, 2)
logits_mma_kernel(const float* __restrict__ enc,
                  const float* __restrict__ W_out,
                  float* __restrict__ logits) {
    extern __shared__ float sm[];
    float* sA     = sm;                       // [2][4096] floats
    uint4* sB     = (uint4*)(sm + 8192);      // [2][1024] uint4
    float* s_dec  = sm + 16384;
    float* s_wout = sm + 16896;
    float* s_part = sm + 17408;

    int tid = threadIdx.x;
    int lane = tid & 31;
    int wid = tid >> 5;
    int mw = wid & 3;     // 0..3  -> rows mw*32..
    int nw = wid >> 2;    // 0..1  -> n8 offset nw*8 within the 128-col chunk

    int b  = blockIdx.x >> 5;
    int st = blockIdx.x & 31;
    long rowbase = (long)b * S + (long)st * 128;
    const float* encBase = enc + rowbase * E;

    for (int i = tid; i < H; i += 256) {
        s_dec[i]  = g_decoded[b * H + i];
        s_wout[i] = W_out[i];
    }

    // staging helper: A (4 x cp.async) + B (4 x cp.async) per thread per kc
    auto stage = [&](int nc, int kc, int buf) {
#pragma unroll
        for (int it = 0; it < 4; it++) {
            int fidx = tid + it * 256;          // 0..1023 float4s
            int row = fidx >> 3;
            int kw  = fidx & 7;
            const float* src = encBase + (long)row * E + kc * 32 + kw * 4;
            uint32_t dst = smem_u32(&sA[buf * 4096 + row * 32 +
                                        ((kw ^ (row & 7)) << 2)]);
            CP_ASYNC16(dst, src);
        }
#pragma unroll
        for (int it = 0; it < 4; it++) {
            int f = tid + it * 256;             // 0..1023 uint4s
            int k16rel = f >> 9;
            int r = f & 511;                    // n8rel*32 + lane
            const uint4* src = &g_WBh[(kc * 2 + k16rel) * 2048 + nc * 512 + r];
            uint32_t dst = smem_u32(&sB[buf * 1024 + f]);
            CP_ASYNC16(dst, (const float*)src);
        }
        CP_COMMIT();
    };

    float rowsum[4] = {0.f, 0.f, 0.f, 0.f};

    for (int nc = 0; nc < 4; nc++) {
        float acc[2][8][4];
#pragma unroll
        for (int mi = 0; mi < 2; mi++)
#pragma unroll
            for (int j = 0; j < 8; j++)
#pragma unroll
                for (int r = 0; r < 4; r++) acc[mi][j][r] = 0.f;

        stage(nc, 0, 0);

        for (int kc = 0; kc < 16; kc++) {
            if (kc < 15) { stage(nc, kc + 1, (kc + 1) & 1); CP_WAIT(1); }
            else         { CP_WAIT(0); }
            __syncthreads();
            const float* A  = sA + (kc & 1) * 4096;
            const uint4* Bs = sB + (kc & 1) * 1024;

#pragma unroll
            for (int kk = 0; kk < 2; kk++) {
                // B fragments from smem: 8 conflict-free LDS.128
                uint4 bc[8];
#pragma unroll
                for (int j = 0; j < 8; j++)
                    bc[j] = Bs[kk * 512 + (nw * 8 + j) * 32 + lane];

                // A fragments (hi & lo) for 2 m16 tiles, fp16 split in regs
                uint32_t aH[2][4], aL[2][4];
                int c0 = kk * 16 + (lane & 3) * 2;
#pragma unroll
                for (int mi = 0; mi < 2; mi++) {
                    int r0 = mw * 32 + mi * 16 + (lane >> 2);
                    int r1 = r0 + 8;
                    float2 v00 = *(const float2*)&A[a_idx(r0, c0)];
                    float2 v10 = *(const float2*)&A[a_idx(r1, c0)];
                    float2 v01 = *(const float2*)&A[a_idx(r0, c0 + 8)];
                    float2 v11 = *(const float2*)&A[a_idx(r1, c0 + 8)];
                    split_h2(v00.x, v00.y, aH[mi][0], aL[mi][0]);
                    split_h2(v10.x, v10.y, aH[mi][1], aL[mi][1]);
                    split_h2(v01.x, v01.y, aH[mi][2], aL[mi][2]);
                    split_h2(v11.x, v11.y, aH[mi][3], aL[mi][3]);
                }

                // hi*hi
#pragma unroll
                for (int mi = 0; mi < 2; mi++)
#pragma unroll
                    for (int j = 0; j < 8; j++)
                        MMA_F16(acc[mi][j], aH[mi], bc[j].x, bc[j].y);
                // lo*hi
#pragma unroll
                for (int mi = 0; mi < 2; mi++)
#pragma unroll
                    for (int j = 0; j < 8; j++)
                        MMA_F16(acc[mi][j], aL[mi], bc[j].x, bc[j].y);
                // hi*lo
#pragma unroll
                for (int mi = 0; mi < 2; mi++)
#pragma unroll
                    for (int j = 0; j < 8; j++)
                        MMA_F16(acc[mi][j], aH[mi], bc[j].z, bc[j].w);
            }
            __syncthreads();
        }

        // epilogue for this N-chunk: tanh(acc + dec) * wout -> rowsum
#pragma unroll
        for (int mi = 0; mi < 2; mi++)
#pragma unroll
            for (int j = 0; j < 8; j++)
#pragma unroll
                for (int r = 0; r < 4; r++) {
                    int col = nc * 128 + nw * 64 + j * 8 + (lane & 3) * 2 + (r & 1);
                    float x = acc[mi][j][r] + s_dec[col];
                    rowsum[mi * 2 + (r >> 1)] += tanh_fast(x) * s_wout[col];
                }
    }

    // reduce rowsum: over lane&3 (shfl), then over nw (smem)
#pragma unroll
    for (int i = 0; i < 4; i++) {
        float v = rowsum[i];
        v += __shfl_xor_sync(0xffffffffu, v, 1);
        v += __shfl_xor_sync(0xffffffffu, v, 2);
        rowsum[i] = v;
    }
    if ((lane & 3) == 0) {
#pragma unroll
        for (int i = 0; i < 4; i++) {
            int row = mw * 32 + (i >> 1) * 16 + (lane >> 2) + (i & 1) * 8;
            s_part[nw * 128 + row] = rowsum[i];
        }
    }
    __syncthreads();
    if (tid < 128)
        logits[rowbase + tid] = s_part[tid] + s_part[128 + tid];
}

// ---------------------------------------------------------------------------
// Kernel 3: masked softmax over S, in place
// ---------------------------------------------------------------------------
__global__ void softmax_kernel(const int* __restrict__ mask,
                               float* __restrict__ probs) {
    int b = blockIdx.x;
    int t = threadIdx.x;
    __shared__ float red[32];
    float l[4];
#pragma unroll
    for (int i = 0; i < 4; i++) {
        int s = t + i * 1024;
        float v = probs[(long)b * S + s];
        l[i] = (mask[(long)b * S + s] == 0) ? NEGV : v;
    }
    float m = fmaxf(fmaxf(l[0], l[1]), fmaxf(l[2], l[3]));
#pragma unroll
    for (int off = 16; off > 0; off >>= 1)
        m = fmaxf(m, __shfl_xor_sync(0xffffffffu, m, off));
    if ((t & 31) == 0) red[t >> 5] = m;
    __syncthreads();
    if (t < 32) {
        float v = red[t];
#pragma unroll
        for (int off = 16; off > 0; off >>= 1)
            v = fmaxf(v, __shfl_xor_sync(0xffffffffu, v, off));
        red[t] = v;
    }
    __syncthreads();
    m = red[0];
    __syncthreads();
    float e[4];
    float sum = 0.f;
#pragma unroll
    for (int i = 0; i < 4; i++) { e[i] = expf(l[i] - m); sum += e[i]; }
#pragma unroll
    for (int off = 16; off > 0; off >>= 1)
        sum += __shfl_xor_sync(0xffffffffu, sum, off);
    if ((t & 31) == 0) red[t >> 5] = sum;
    __syncthreads();
    if (t < 32) {
        float v = red[t];
#pragma unroll
        for (int off = 16; off > 0; off >>= 1)
            v += __shfl_xor_sync(0xffffffffu, v, off);
        red[t] = v;
    }
    __syncthreads();
    float inv = 1.f / red[0];
#pragma unroll
    for (int i = 0; i < 4; i++)
        probs[(long)b * S + t + i * 1024] = e[i] * inv;
}

// ---------------------------------------------------------------------------
// Kernel 4: partial attn over 128-row s-chunks, float4 per thread
// ---------------------------------------------------------------------------
__global__ void attn_part_kernel(const float* __restrict__ enc,
                                 const float* __restrict__ probs) {
    int sc = blockIdx.x & 31;
    int b  = blockIdx.x >> 5;
    int t  = threadIdx.x;   // 0..127
    __shared__ float p_s[128];
    p_s[t] = probs[(long)b * S + sc * 128 + t];
    __syncthreads();
    const float4* encp = (const float4*)(enc + ((long)b * S + (long)sc * 128) * E) + t;
    float4 acc = make_float4(0.f, 0.f, 0.f, 0.f);
#pragma unroll 8
    for (int s = 0; s < 128; s++) {
        float4 v = encp[(long)s * (E / 4)];
        float p = p_s[s];
        acc.x += p * v.x; acc.y += p * v.y;
        acc.z += p * v.z; acc.w += p * v.w;
    }
    ((float4*)g_attn_part)[((long)b * 32 + sc) * (E / 4) + t] = acc;
}

// ---------------------------------------------------------------------------
// Kernel 5: fixed-order reduction -> attn (float4)
// ---------------------------------------------------------------------------
__global__ void attn_reduce_kernel(float* __restrict__ attn) {
    int b = blockIdx.x;
    int t = threadIdx.x;   // 0..127
    float4 s = make_float4(0.f, 0.f, 0.f, 0.f);
#pragma unroll
    for (int c = 0; c < 32; c++) {
        float4 v = ((const float4*)g_attn_part)[((long)b * 32 + c) * (E / 4) + t];
        s.x += v.x; s.y += v.y; s.z += v.z; s.w += v.w;
    }
    ((float4*)attn)[b * (E / 4) + t] = s;
}

// ---------------------------------------------------------------------------
extern "C" void kernel_launch(void* const* d_in, const int* in_sizes, int n_in,
                              void* d_out, int out_size) {
    const float* enc   = (const float*)d_in[0];
    const float* dec   = (const float*)d_in[1];
    const int*   mask  = (const int*)  d_in[2];
    const float* W_enc = (const float*)d_in[3];
    const float* W_dec = (const float*)d_in[4];
    const float* W_out = (const float*)d_in[5];

    float* attn  = (float*)d_out;       // [B,E]
    float* probs = attn + B * E;        // [B,S] (logits written in place)

    cudaFuncSetAttribute(logits_mma_kernel,
                         cudaFuncAttributeMaxDynamicSharedMemorySize, SMF_TOTAL);

    wsplit_kernel<<<256, 256>>>(W_enc);
    decode_kernel<<<B, 512>>>(dec, W_dec);
    logits_mma_kernel<<<B * (S / 128), 256, SMF_TOTAL>>>(enc, W_out, probs);
    softmax_kernel<<<B, 1024>>>(mask, probs);
    attn_part_kernel<<<B * 32, 128>>>(enc, probs);
    attn_reduce_kernel<<<B, 128>>>(attn);
}